// round 15
// baseline (speedup 1.0000x reference)
#include <cuda_runtime.h>
#include <cuda_bf16.h>
#include <cstdint>

// f_z[b,i] = z[b,i] + sum_{j<i} h[b, i*(i-1)/2 + j] * z[b,j]
// Trunk: pair rows (i, 513-i) -> same off%4 class m; z register quads from
// shifted zero-padded smem copies Z_m serve every h quad with the lane's own
// regs (no per-quad LDS, no shfl in steady state).
// R15: full software pipeline -- load pair1 (X), z-fill (overlaps X latency),
// load pair2 (Y), consume X (Y's 2KB in flight the whole time), consume Y.
// One DRAM stall per warp instead of two. 3 CTAs/SM (84-reg budget).

#define DIM 512
#define HLEN 130816
#define THREADS 256
#define ZPADF 640
#define FULL 0xffffffffu

__device__ __forceinline__ unsigned off_of(int r) {
    return (unsigned)(r * (r - 1) / 2);
}

struct HQ {
    float4 B0, B1, B2, B3, B4, A0, A1, A2;
    int m, ea, eb, nqa, nqb;
};

// map work unit w (0..255 per batch) to a same-mis row pair
__device__ __forceinline__ void map_unit(int w, int& ia, int& ib) {
    if (w >= 2)      { ia = w;   ib = 513 - w; }
    else             { ia = 257; ib = 256;     }   // w==1 (w==0 inactive)
}

__device__ __forceinline__ void hq_load(const float* __restrict__ hbase,
                                        int ia, int ib, int lane, bool active,
                                        HQ& X)
{
    const unsigned offa = off_of(ia);
    const unsigned offb = off_of(ib);
    X.m  = (int)(offa & 3u);
    X.ea = ia + X.m;
    X.eb = ib + X.m;
    X.nqa = active ? ((X.ea + 3) >> 2) : 0;    // <= 65
    X.nqb = active ? ((X.eb + 3) >> 2) : 0;    // 64..129 when active

    const float4* ha4 = (const float4*)(hbase + (offa & ~3u));
    const float4* hb4 = (const float4*)(hbase + (offb & ~3u));
    const float4 zf = make_float4(0.f, 0.f, 0.f, 0.f);

    X.B0 = (lane       < X.nqb) ? __ldcs(hb4 + lane)       : zf;
    X.B1 = (lane + 32  < X.nqb) ? __ldcs(hb4 + lane + 32)  : zf;
    X.B2 = (lane + 64  < X.nqb) ? __ldcs(hb4 + lane + 64)  : zf;
    X.B3 = (lane + 96  < X.nqb) ? __ldcs(hb4 + lane + 96)  : zf;
    X.B4 = (lane + 128 < X.nqb) ? __ldcs(hb4 + lane + 128) : zf;
    X.A0 = (lane       < X.nqa) ? __ldcs(ha4 + lane)       : zf;
    X.A1 = (lane + 32  < X.nqa) ? __ldcs(ha4 + lane + 32)  : zf;
    X.A2 = (lane + 64  < X.nqa) ? __ldcs(ha4 + lane + 64)  : zf;
}

__device__ __forceinline__ void hq_consume(const HQ& X,
                                           const float* __restrict__ zsh,
                                           float* __restrict__ ob,
                                           int ia, int ib, int lane)
{
    const int vba = X.ea >> 2, ca = X.ea & 3;
    const int vbb = X.eb >> 2, cb = X.eb & 3;

    const float4* Zm4 = (const float4*)(zsh + X.m * ZPADF);
    float4 zq0 = Zm4[lane];
    float4 zq1 = Zm4[lane + 32];
    float4 zq2 = Zm4[lane + 64];
    float4 zq3 = Zm4[lane + 96];
    float4 zq4 = Zm4[lane + 128];

    float s0 = 0.f, s1 = 0.f, s2 = 0.f, s3 = 0.f;
    #define STEP(Q, ZV) {                                       \
        s0 = fmaf(Q.x, ZV.x, s0);                               \
        s1 = fmaf(Q.y, ZV.y, s1);                               \
        s2 = fmaf(Q.z, ZV.z, s2);                               \
        s3 = fmaf(Q.w, ZV.w, s3);                               \
    }
    STEP(X.B0, zq0) STEP(X.B1, zq1) STEP(X.B2, zq2)
    STEP(X.B3, zq3) STEP(X.B4, zq4)
    float sumb = (s0 + s1) + (s2 + s3);

    s0 = s1 = s2 = s3 = 0.f;
    STEP(X.A0, zq0) STEP(X.A1, zq1) STEP(X.A2, zq2)
    float suma = (s0 + s1) + (s2 + s3);
    #undef STEP

    // tail-junk subtract (components k >= c of boundary quad), all regs
    if (cb && lane == (vbb & 31)) {            // vbb>>5 in {2,3,4}
        const int st = vbb >> 5;
        float4 Q  = (st == 2) ? X.B2 : (st == 3) ? X.B3 : X.B4;
        float4 zt = (st == 2) ? zq2  : (st == 3) ? zq3  : zq4;
        float jnk = Q.w * zt.w;
        if (cb <= 2) jnk = fmaf(Q.z, zt.z, jnk);
        if (cb <= 1) jnk = fmaf(Q.y, zt.y, jnk);
        sumb -= jnk;
    }
    if (ca && lane == (vba & 31)) {            // vba>>5 in {0,1,2}
        const int st = vba >> 5;
        float4 Q  = (st == 0) ? X.A0 : (st == 1) ? X.A1 : X.A2;
        float4 zt = (st == 0) ? zq0  : (st == 1) ? zq1  : zq2;
        float jnk = Q.w * zt.w;
        if (ca <= 2) jnk = fmaf(Q.z, zt.z, jnk);
        if (ca <= 1) jnk = fmaf(Q.y, zt.y, jnk);
        suma -= jnk;
    }

    #pragma unroll
    for (int o = 16; o; o >>= 1) {
        suma += __shfl_xor_sync(FULL, suma, o);
        sumb += __shfl_xor_sync(FULL, sumb, o);
    }

    if (lane == 0) {
        ob[ia] = zsh[ia] + suma;               // Z_0 is plain z
        ob[ib] = zsh[ib] + sumb;
    }
}

__global__ __launch_bounds__(THREADS, 3) void LinearMap_kernel(
    const float* __restrict__ z,
    const float* __restrict__ h,
    float* __restrict__ out,
    int out_size)
{
    __shared__ float zsh[4 * ZPADF];    // shifted copy m at m*ZPADF

    const int b    = blockIdx.x >> 4;   // / 16
    const int cg   = blockIdx.x & 15;
    const int tid  = threadIdx.x;
    const int warp = tid >> 5;
    const int lane = tid & 31;

    const float* hbase = h + (size_t)b * HLEN;
    const int base = cg * 16;
    const int w1 = base + warp;
    const int w2 = base + 8 + warp;     // always >= 8 (generic pair)

    // ---- stage 1: pair-1 loads in flight ----
    int ia1, ib1; map_unit(w1, ia1, ib1);
    HQ X;
    hq_load(hbase, ia1, ib1, lane, w1 >= 1, X);

    // ---- z fill (overlaps pair-1 DRAM latency) ----
    {
        int m = tid >> 6;               // zero pads: [512,640) + heads [0,m)
        int j = 512 + (tid & 63);
        zsh[m * ZPADF + j]      = 0.f;
        zsh[m * ZPADF + j + 64] = 0.f;
        if (tid < 16) {
            int mm = tid >> 2, k = tid & 3;
            if (k < mm) zsh[mm * ZPADF + k] = 0.f;
        }
    }
    __syncthreads();
    {
        const float* zb = z + (size_t)b * DIM;
        #pragma unroll
        for (int j = tid; j < DIM; j += THREADS) {
            float v = zb[j];
            zsh[j]                 = v;
            zsh[ZPADF     + j + 1] = v;
            zsh[2 * ZPADF + j + 2] = v;
            zsh[3 * ZPADF + j + 3] = v;
        }
    }
    __syncthreads();

    // ---- stage 2: pair-2 loads in flight BEFORE consuming pair 1 ----
    int ia2, ib2; map_unit(w2, ia2, ib2);
    HQ Y;
    hq_load(hbase, ia2, ib2, lane, true, Y);

    float* ob = out + (size_t)b * DIM;

    // ---- stage 3: consume pair 1 (Y covers DRAM the whole time) ----
    if (w1 >= 1) hq_consume(X, zsh, ob, ia1, ib1, lane);
    else if (lane == 0) {                      // w1==0: rows 0, 1
        ob[0] = zsh[0];
        ob[1] = zsh[1] + hbase[0] * zsh[0];
    }

    // ---- stage 4: consume pair 2 ----
    hq_consume(Y, zsh, ob, ia2, ib2, lane);

    // logdet / tail zeroing (d_out is poisoned)
    if (blockIdx.x == 0) {
        const int nfz = (int)(gridDim.x >> 4) * DIM;
        for (int k = nfz + tid; k < out_size; k += THREADS) out[k] = 0.0f;
    }
}

extern "C" void kernel_launch(void* const* d_in, const int* in_sizes, int n_in,
                              void* d_out, int out_size)
{
    const float* z = (const float*)d_in[0];   // [batch, 512]
    const float* h = (const float*)d_in[1];   // [batch, 130816]
    float* out = (float*)d_out;

    const int batch = in_sizes[0] / DIM;      // 256

    dim3 grid(batch * 16);                    // 4096 identical CTAs
    LinearMap_kernel<<<grid, THREADS>>>(z, h, out, out_size);
}

// round 16
// speedup vs baseline: 1.2354x; 1.2354x over previous
#include <cuda_runtime.h>
#include <cuda_bf16.h>
#include <cstdint>

// f_z[b,i] = z[b,i] + sum_{j<i} h[b, i*(i-1)/2 + j] * z[b,j]
// Trunk = R14: pair rows (i, 513-i) -> same off%4 class m; z register quads
// from shifted zero-padded smem copies Z_m serve every h quad with the
// lane's own regs. Pair-1 h loads hoisted above z-fill (register path).
// R16: pair-2 is prefetched via cp.async (LDGSTS) into a per-warp smem
// buffer BEFORE the z-fill -- engine-side in-flight bytes, zero register
// cost -- and consumed from smem after pair-1. One DRAM stall per warp,
// without R15's register/occupancy collapse.

#define DIM 512
#define HLEN 130816
#define THREADS 256
#define ZPADF 640
#define FULL 0xffffffffu
#define YA_Q 68            // quads for pair-2 short row (max 65)
#define YB_Q 132           // quads for pair-2 long row (max 129)

__device__ __forceinline__ unsigned off_of(int r) {
    return (unsigned)(r * (r - 1) / 2);
}
__device__ __forceinline__ void cpasync16(void* sdst, const void* gsrc) {
    unsigned d = (unsigned)__cvta_generic_to_shared(sdst);
    asm volatile("cp.async.cg.shared.global [%0], [%1], 16;"
                 :: "r"(d), "l"(gsrc) : "memory");
}

struct HQ {
    float4 B0, B1, B2, B3, B4, A0, A1, A2;
    int m, ea, eb, nqa, nqb;
};

__device__ __forceinline__ void map_unit(int w, int& ia, int& ib) {
    if (w >= 2) { ia = w;   ib = 513 - w; }
    else        { ia = 257; ib = 256;     }   // w==1 (w==0 handled separately)
}

__device__ __forceinline__ void hq_load(const float* __restrict__ hbase,
                                        int ia, int ib, int lane, bool active,
                                        HQ& X)
{
    const unsigned offa = off_of(ia);
    const unsigned offb = off_of(ib);
    X.m  = (int)(offa & 3u);
    X.ea = ia + X.m;
    X.eb = ib + X.m;
    X.nqa = active ? ((X.ea + 3) >> 2) : 0;
    X.nqb = active ? ((X.eb + 3) >> 2) : 0;

    const float4* ha4 = (const float4*)(hbase + (offa & ~3u));
    const float4* hb4 = (const float4*)(hbase + (offb & ~3u));
    const float4 zf = make_float4(0.f, 0.f, 0.f, 0.f);

    X.B0 = (lane       < X.nqb) ? __ldcs(hb4 + lane)       : zf;
    X.B1 = (lane + 32  < X.nqb) ? __ldcs(hb4 + lane + 32)  : zf;
    X.B2 = (lane + 64  < X.nqb) ? __ldcs(hb4 + lane + 64)  : zf;
    X.B3 = (lane + 96  < X.nqb) ? __ldcs(hb4 + lane + 96)  : zf;
    X.B4 = (lane + 128 < X.nqb) ? __ldcs(hb4 + lane + 128) : zf;
    X.A0 = (lane       < X.nqa) ? __ldcs(ha4 + lane)       : zf;
    X.A1 = (lane + 32  < X.nqa) ? __ldcs(ha4 + lane + 32)  : zf;
    X.A2 = (lane + 64  < X.nqa) ? __ldcs(ha4 + lane + 64)  : zf;
}

// shared consume core: quads already in X
__device__ __forceinline__ void hq_consume(const HQ& X,
                                           const float* __restrict__ zsh,
                                           float* __restrict__ ob,
                                           int ia, int ib, int lane)
{
    const int vba = X.ea >> 2, ca = X.ea & 3;
    const int vbb = X.eb >> 2, cb = X.eb & 3;

    const float4* Zm4 = (const float4*)(zsh + X.m * ZPADF);
    float4 zq0 = Zm4[lane];
    float4 zq1 = Zm4[lane + 32];
    float4 zq2 = Zm4[lane + 64];
    float4 zq3 = Zm4[lane + 96];
    float4 zq4 = Zm4[lane + 128];

    float s0 = 0.f, s1 = 0.f, s2 = 0.f, s3 = 0.f;
    #define STEP(Q, ZV) {                                       \
        s0 = fmaf(Q.x, ZV.x, s0);                               \
        s1 = fmaf(Q.y, ZV.y, s1);                               \
        s2 = fmaf(Q.z, ZV.z, s2);                               \
        s3 = fmaf(Q.w, ZV.w, s3);                               \
    }
    STEP(X.B0, zq0) STEP(X.B1, zq1) STEP(X.B2, zq2)
    STEP(X.B3, zq3) STEP(X.B4, zq4)
    float sumb = (s0 + s1) + (s2 + s3);

    s0 = s1 = s2 = s3 = 0.f;
    STEP(X.A0, zq0) STEP(X.A1, zq1) STEP(X.A2, zq2)
    float suma = (s0 + s1) + (s2 + s3);
    #undef STEP

    if (cb && lane == (vbb & 31)) {
        const int st = vbb >> 5;                // 2..4
        float4 Q  = (st == 2) ? X.B2 : (st == 3) ? X.B3 : X.B4;
        float4 zt = (st == 2) ? zq2  : (st == 3) ? zq3  : zq4;
        float jnk = Q.w * zt.w;
        if (cb <= 2) jnk = fmaf(Q.z, zt.z, jnk);
        if (cb <= 1) jnk = fmaf(Q.y, zt.y, jnk);
        sumb -= jnk;
    }
    if (ca && lane == (vba & 31)) {
        const int st = vba >> 5;                // 0..2
        float4 Q  = (st == 0) ? X.A0 : (st == 1) ? X.A1 : X.A2;
        float4 zt = (st == 0) ? zq0  : (st == 1) ? zq1  : zq2;
        float jnk = Q.w * zt.w;
        if (ca <= 2) jnk = fmaf(Q.z, zt.z, jnk);
        if (ca <= 1) jnk = fmaf(Q.y, zt.y, jnk);
        suma -= jnk;
    }

    #pragma unroll
    for (int o = 16; o; o >>= 1) {
        suma += __shfl_xor_sync(FULL, suma, o);
        sumb += __shfl_xor_sync(FULL, sumb, o);
    }
    if (lane == 0) {
        ob[ia] = zsh[ia] + suma;
        ob[ib] = zsh[ib] + sumb;
    }
}

// consume pair from SMEM-staged quads
__device__ __forceinline__ void consume_smem(const float4* __restrict__ ha4,
                                             const float4* __restrict__ hb4,
                                             int m, int ia, int ib,
                                             const float* __restrict__ zsh,
                                             float* __restrict__ ob, int lane)
{
    HQ X;
    X.m = m; X.ea = ia + m; X.eb = ib + m;
    X.nqa = (X.ea + 3) >> 2;
    X.nqb = (X.eb + 3) >> 2;
    const float4 zf = make_float4(0.f, 0.f, 0.f, 0.f);
    X.B0 = hb4[lane];                           // nqb >= 64
    X.B1 = hb4[lane + 32];
    X.B2 = (lane + 64  < X.nqb) ? hb4[lane + 64]  : zf;
    X.B3 = (lane + 96  < X.nqb) ? hb4[lane + 96]  : zf;
    X.B4 = (lane + 128 < X.nqb) ? hb4[lane + 128] : zf;
    X.A0 = (lane       < X.nqa) ? ha4[lane]       : zf;
    X.A1 = (lane + 32  < X.nqa) ? ha4[lane + 32]  : zf;
    X.A2 = (lane + 64  < X.nqa) ? ha4[lane + 64]  : zf;
    hq_consume(X, zsh, ob, ia, ib, lane);
}

__global__ __launch_bounds__(THREADS, 4) void LinearMap_kernel(
    const float* __restrict__ z,
    const float* __restrict__ h,
    float* __restrict__ out,
    int out_size)
{
    __shared__ float zsh[4 * ZPADF];
    __shared__ __align__(16) float4 ybuf[8][YA_Q + YB_Q];   // per-warp stage

    const int b    = blockIdx.x >> 4;   // / 16
    const int cg   = blockIdx.x & 15;
    const int tid  = threadIdx.x;
    const int warp = tid >> 5;
    const int lane = tid & 31;

    const float* hbase = h + (size_t)b * HLEN;
    const int base = cg * 16;
    const int w1 = base + warp;
    const int w2 = base + 8 + warp;     // in [8,255]: always generic pair

    // ---- stage 1: pair-1 register loads in flight ----
    int ia1, ib1; map_unit(w1, ia1, ib1);
    HQ X;
    hq_load(hbase, ia1, ib1, lane, w1 >= 1, X);

    // ---- stage 2: pair-2 cp.async into per-warp smem (engine-side) ----
    const int ia2 = w2, ib2 = 513 - w2;
    const unsigned offa2 = off_of(ia2), offb2 = off_of(ib2);
    const int m2 = (int)(offa2 & 3u);
    const int nqa2 = (ia2 + m2 + 3) >> 2;       // <= 65
    const int nqb2 = (ib2 + m2 + 3) >> 2;       // <= 129
    {
        const float4* ga4 = (const float4*)(hbase + (offa2 & ~3u));
        const float4* gb4 = (const float4*)(hbase + (offb2 & ~3u));
        float4* ya = &ybuf[warp][0];
        float4* yb = &ybuf[warp][YA_Q];
        #pragma unroll
        for (int k = 0; k < 3; ++k) {
            int q = lane + 32 * k;
            if (q < nqa2) cpasync16(ya + q, ga4 + q);
        }
        #pragma unroll
        for (int k = 0; k < 5; ++k) {
            int q = lane + 32 * k;
            if (q < nqb2) cpasync16(yb + q, gb4 + q);
        }
        asm volatile("cp.async.commit_group;" ::: "memory");
    }

    // ---- z fill (overlaps both loads) ----
    {
        int m = tid >> 6;
        int j = 512 + (tid & 63);
        zsh[m * ZPADF + j]      = 0.f;
        zsh[m * ZPADF + j + 64] = 0.f;
        if (tid < 16) {
            int mm = tid >> 2, k = tid & 3;
            if (k < mm) zsh[mm * ZPADF + k] = 0.f;
        }
    }
    __syncthreads();
    {
        const float* zb = z + (size_t)b * DIM;
        #pragma unroll
        for (int j = tid; j < DIM; j += THREADS) {
            float v = zb[j];
            zsh[j]                 = v;
            zsh[ZPADF     + j + 1] = v;
            zsh[2 * ZPADF + j + 2] = v;
            zsh[3 * ZPADF + j + 3] = v;
        }
    }
    __syncthreads();

    float* ob = out + (size_t)b * DIM;

    // ---- stage 3: consume pair 1 (pair-2 flying engine-side) ----
    if (w1 >= 1) hq_consume(X, zsh, ob, ia1, ib1, lane);
    else if (lane == 0) {                      // w1==0: rows 0, 1
        ob[0] = zsh[0];
        ob[1] = zsh[1] + hbase[0] * zsh[0];
    }

    // ---- stage 4: consume pair 2 from smem ----
    asm volatile("cp.async.wait_group 0;" ::: "memory");
    __syncwarp();
    consume_smem(&ybuf[warp][0], &ybuf[warp][YA_Q], m2, ia2, ib2,
                 zsh, ob, lane);

    // logdet / tail zeroing (d_out is poisoned)
    if (blockIdx.x == 0) {
        const int nfz = (int)(gridDim.x >> 4) * DIM;
        for (int k = nfz + tid; k < out_size; k += THREADS) out[k] = 0.0f;
    }
}

extern "C" void kernel_launch(void* const* d_in, const int* in_sizes, int n_in,
                              void* d_out, int out_size)
{
    const float* z = (const float*)d_in[0];   // [batch, 512]
    const float* h = (const float*)d_in[1];   // [batch, 130816]
    float* out = (float*)d_out;

    const int batch = in_sizes[0] / DIM;      // 256

    dim3 grid(batch * 16);                    // 4096 identical CTAs
    LinearMap_kernel<<<grid, THREADS>>>(z, h, out, out_size);
}